// round 5
// baseline (speedup 1.0000x reference)
#include <cuda_runtime.h>
#include <cuda_fp16.h>

// ---------------------------------------------------------------------------
// NetMHCpan BiLSTM:  pep BiLSTM (T=15) + HLA BiLSTM (T=372), H=1024,
// then MLP 4096 -> 4096 (relu) -> 1.
//
// Persistent cooperative kernel. 128 CTAs (2 directions x 64), each CTA owns
// 16 hidden units; its 64 gate rows of whh live in SMEM as fp16 (128 KB ->
// occupancy 1 -> all 128 CTAs co-resident -> spin barrier deadlock-free on a
// full chip; the spin is BOUNDED so reduced-SM environments fail fast with
// wrong results instead of hanging the container).
// Phase 0 runs both pep directions (15 steps), phase 1 reloads SMEM weights
// and runs both HLA directions (372 steps). h is broadcast through L2 with
// step-parity double buffering; per-step arrival counters form the barrier.
// ---------------------------------------------------------------------------

#define H      1024
#define G4     4096
#define LPEP   15
#define LHLA   372
#define GCTA   64     // CTAs per direction
#define NHU    16     // hidden units per CTA
#define NROWS  64     // gate rows per CTA (4 gates * NHU)
#define NTHR   256
#define NBLK   128    // total persistent CTAs
#define SPIN_LIMIT (1u << 20)   // bounded spin: fail fast instead of deadlock

// SMEM: weights 64*1024 halves (131072 B) + h (4096 B) + gacc (256 B)
#define SMEM_BYTES (NROWS * H * 2 + H * 4 + NROWS * 4)

struct Ptrs {
    const float* wih[4];
    const float* whh[4];
    const float* bih[4];
    const float* bhh[4];
};

// -------------------- device scratch (no allocations allowed) ---------------
__device__ float    g_xg[4 * LHLA * G4];   // input projections + biases (24.4 MB)
__device__ float    g_h[4 * 2 * H];        // per-direction double-buffered h
__device__ unsigned g_bar[4 * 400];        // per-direction per-step arrival counters
__device__ float    g_h1[G4];              // MLP hidden activations

// ---------------------------------------------------------------------------
// Prep: zero barriers/h, and precompute xg[d][t][row] = x_t @ wih.T + bih + bhh
// d: 0=pep_f 1=pep_b 2=hla_f 3=hla_b (backward dirs consume reversed input).
// ---------------------------------------------------------------------------
__global__ void prep_kernel(const float* __restrict__ in_pep,
                            const float* __restrict__ in_hla,
                            Ptrs p)
{
    __shared__ float sx[LHLA * 21];    // 31.2 KB
    const int bid = blockIdx.x;
    const int tid = threadIdx.x;

    if (bid >= 64) {
        if (bid == 64) {
            for (int i = tid; i < 4 * 400; i += NTHR) g_bar[i] = 0u;
        } else {
            for (int i = tid; i < 4 * 2 * H; i += NTHR) g_h[i] = 0.0f;
        }
        return;
    }

    const int d  = bid >> 4;          // direction
    const int rb = bid & 15;          // row block (256 rows each)
    const int T  = (d < 2) ? LPEP : LHLA;
    const float* src = (d < 2) ? in_pep : in_hla;
    const bool rev = (d & 1);

    for (int i = tid; i < T * 21; i += NTHR) {
        int t = i / 21, j = i - t * 21;
        int ts = rev ? (T - 1 - t) : t;
        sx[t * 21 + j] = src[ts * 21 + j];
    }
    __syncthreads();

    const int row = rb * 256 + tid;
    float w[21];
    const float* wp = p.wih[d] + (size_t)row * 21;
#pragma unroll
    for (int j = 0; j < 21; ++j) w[j] = wp[j];
    const float b = p.bih[d][row] + p.bhh[d][row];

    float* out = g_xg + (size_t)d * LHLA * G4 + row;
    for (int t = 0; t < T; ++t) {
        float acc = b;
#pragma unroll
        for (int j = 0; j < 21; ++j) acc = fmaf(w[j], sx[t * 21 + j], acc);
        out[(size_t)t * G4] = acc;
    }
}

// ---------------------------------------------------------------------------
// Persistent BiLSTM kernel.
// ---------------------------------------------------------------------------
__global__ void __launch_bounds__(NTHR, 1) lstm_kernel(Ptrs p)
{
    extern __shared__ unsigned char smem[];
    __half2* wt   = (__half2*)smem;                        // [64][512] half2
    float*   h_sm = (float*)(smem + NROWS * H * 2);        // [1024]
    float*   gacc = h_sm + H;                              // [64]

    const int tid  = threadIdx.x;
    const int lane = tid & 31;
    const int warp = tid >> 5;
    const int grp  = blockIdx.x >> 6;   // 0 or 1: direction within phase
    const int gid  = blockIdx.x & 63;   // CTA index within direction group

    for (int phase = 0; phase < 2; ++phase) {
        const int d = phase * 2 + grp;
        const int T = phase ? LHLA : LPEP;
        const float* whh = p.whh[d];

        // ---- load this CTA's 64 gate rows of whh into SMEM as fp16 ----
        for (int r = warp; r < NROWS; r += 8) {
            const int u = r & 15, g = r >> 4;
            const float4* src = (const float4*)(whh + ((size_t)(g * H + gid * NHU + u)) * H);
            __half2* dst = wt + r * 512;
            for (int k = lane; k < 256; k += 32) {
                float4 f = src[k];
                dst[2 * k]     = __floats2half2_rn(f.x, f.y);
                dst[2 * k + 1] = __floats2half2_rn(f.z, f.w);
            }
        }
        float c_reg = 0.0f;                                // cell state (tid < 16)
        volatile unsigned* bar = (volatile unsigned*)(g_bar + d * 400);
        float* hbuf = g_h + d * 2 * H;
        const float* xg_d = g_xg + (size_t)d * LHLA * G4 + gid * NHU;
        __syncthreads();

        for (int t = 0; t < T; ++t) {
            // prefetch xg for this step (independent of h)
            float xg0 = 0.f, xg1 = 0.f, xg2 = 0.f, xg3 = 0.f;
            if (tid < NHU) {
                const float* xp = xg_d + (size_t)t * G4 + tid;
                xg0 = __ldg(xp);
                xg1 = __ldg(xp + H);
                xg2 = __ldg(xp + 2 * H);
                xg3 = __ldg(xp + 3 * H);
            }

            // wait for h(t) from all 64 CTAs of this direction (bounded spin:
            // if co-residency is ever violated we produce wrong results fast
            // instead of hanging the container for 600 s)
            if (t > 0) {
                if (tid == 0) {
                    unsigned spins = 0;
                    while (bar[t] < GCTA && ++spins < SPIN_LIMIT) __nanosleep(20);
                    __threadfence();   // acquire
                }
                __syncthreads();
            }

            // broadcast h(t) into SMEM (L2-coherent loads; L1 may be stale)
            const float4* hsrc = (const float4*)(hbuf + (t & 1) * H);
            float4 hv = __ldcg(hsrc + tid);
            ((float4*)h_sm)[tid] = hv;
            __syncthreads();

            // lane-local h chunk: 4 groups of 8 floats, h[g*256 + lane*8 .. +8]
            float hr[32];
#pragma unroll
            for (int g = 0; g < 4; ++g) {
                ((float4*)hr)[2 * g]     = ((const float4*)h_sm)[g * 64 + lane * 2];
                ((float4*)hr)[2 * g + 1] = ((const float4*)h_sm)[g * 64 + lane * 2 + 1];
            }

            // 8 gate-row dots per warp (rows warp*8 .. warp*8+7)
#pragma unroll
            for (int i = 0; i < 8; ++i) {
                const uint4* wrow = (const uint4*)(wt + (warp * 8 + i) * 512);
                float acc = 0.0f;
#pragma unroll
                for (int g = 0; g < 4; ++g) {
                    // 8 halves: weight cols g*256 + lane*8 .. +7  (uint4 idx g*32+lane)
                    uint4 wq = wrow[g * 32 + lane];
                    float2 f0 = __half22float2(*(const __half2*)&wq.x);
                    float2 f1 = __half22float2(*(const __half2*)&wq.y);
                    float2 f2 = __half22float2(*(const __half2*)&wq.z);
                    float2 f3 = __half22float2(*(const __half2*)&wq.w);
                    acc = fmaf(f0.x, hr[8 * g + 0], acc);
                    acc = fmaf(f0.y, hr[8 * g + 1], acc);
                    acc = fmaf(f1.x, hr[8 * g + 2], acc);
                    acc = fmaf(f1.y, hr[8 * g + 3], acc);
                    acc = fmaf(f2.x, hr[8 * g + 4], acc);
                    acc = fmaf(f2.y, hr[8 * g + 5], acc);
                    acc = fmaf(f3.x, hr[8 * g + 6], acc);
                    acc = fmaf(f3.y, hr[8 * g + 7], acc);
                }
                acc += __shfl_xor_sync(0xffffffffu, acc, 16);
                acc += __shfl_xor_sync(0xffffffffu, acc, 8);
                acc += __shfl_xor_sync(0xffffffffu, acc, 4);
                acc += __shfl_xor_sync(0xffffffffu, acc, 2);
                acc += __shfl_xor_sync(0xffffffffu, acc, 1);
                if (lane == 0) gacc[warp * 8 + i] = acc;   // r = g*16 + u
            }
            __syncthreads();

            // LSTM cell update for this CTA's 16 hidden units
            if (tid < NHU) {
                float zi = gacc[0 * 16 + tid] + xg0;
                float zf = gacc[1 * 16 + tid] + xg1;
                float zg = gacc[2 * 16 + tid] + xg2;
                float zo = gacc[3 * 16 + tid] + xg3;
                float ig = 1.0f / (1.0f + __expf(-zi));
                float fg = 1.0f / (1.0f + __expf(-zf));
                float gg = tanhf(zg);
                float og = 1.0f / (1.0f + __expf(-zo));
                c_reg = fg * c_reg + ig * gg;
                float hn = og * tanhf(c_reg);
                hbuf[((t + 1) & 1) * H + gid * NHU + tid] = hn;
            }
            __threadfence();           // release: h(t+1) visible before arrival
            __syncthreads();
            if (tid == 0)
                atomicAdd((unsigned*)(g_bar + d * 400 + t + 1), 1u);
        }
        __syncthreads();               // all reads of wt done before reload
    }
}

// ---------------------------------------------------------------------------
// MLP: h1 = relu(x @ w1.T + b1), y = h1 @ w2.T + b2.
// x = [pep_f(1024), pep_b, hla_f, hla_b]; pep finals in buf 1, hla in buf 0.
// ---------------------------------------------------------------------------
__global__ void mlp1_kernel(const float* __restrict__ w1, const float* __restrict__ b1)
{
    __shared__ float sx[G4];
    const int tid = threadIdx.x, lane = tid & 31, warp = tid >> 5;

    for (int k = tid; k < G4; k += NTHR) {
        int dd = k >> 10;
        int kk = k & 1023;
        int buf = (dd < 2) ? 1 : 0;    // pep T=15 -> buf 1, hla T=372 -> buf 0
        sx[k] = g_h[dd * 2 * H + buf * H + kk];
    }
    __syncthreads();

#pragma unroll
    for (int rep = 0; rep < 2; ++rep) {
        const int j = blockIdx.x * 16 + rep * 8 + warp;
        const float* wrow = w1 + (size_t)j * G4;
        float acc = 0.0f;
#pragma unroll 8
        for (int i = 0; i < 128; ++i)
            acc = fmaf(wrow[i * 32 + lane], sx[i * 32 + lane], acc);
        acc += __shfl_xor_sync(0xffffffffu, acc, 16);
        acc += __shfl_xor_sync(0xffffffffu, acc, 8);
        acc += __shfl_xor_sync(0xffffffffu, acc, 4);
        acc += __shfl_xor_sync(0xffffffffu, acc, 2);
        acc += __shfl_xor_sync(0xffffffffu, acc, 1);
        if (lane == 0) g_h1[j] = fmaxf(acc + b1[j], 0.0f);
    }
}

__global__ void mlp2_kernel(const float* __restrict__ w2, const float* __restrict__ b2,
                            float* __restrict__ out)
{
    __shared__ float red[32];
    const int tid = threadIdx.x, lane = tid & 31, warp = tid >> 5;
    float acc = 0.0f;
    for (int k = tid; k < G4; k += 1024)
        acc = fmaf(g_h1[k], w2[k], acc);
    acc += __shfl_xor_sync(0xffffffffu, acc, 16);
    acc += __shfl_xor_sync(0xffffffffu, acc, 8);
    acc += __shfl_xor_sync(0xffffffffu, acc, 4);
    acc += __shfl_xor_sync(0xffffffffu, acc, 2);
    acc += __shfl_xor_sync(0xffffffffu, acc, 1);
    if (lane == 0) red[warp] = acc;
    __syncthreads();
    if (warp == 0) {
        float v = red[lane];
        v += __shfl_xor_sync(0xffffffffu, v, 16);
        v += __shfl_xor_sync(0xffffffffu, v, 8);
        v += __shfl_xor_sync(0xffffffffu, v, 4);
        v += __shfl_xor_sync(0xffffffffu, v, 2);
        v += __shfl_xor_sync(0xffffffffu, v, 1);
        if (lane == 0) out[0] = v + b2[0];
    }
}

// ---------------------------------------------------------------------------
extern "C" void kernel_launch(void* const* d_in, const int* in_sizes, int n_in,
                              void* d_out, int out_size)
{
    (void)in_sizes; (void)n_in; (void)out_size;

    const float* in_pep = (const float*)d_in[0];
    const float* in_hla = (const float*)d_in[1];

    Ptrs p;
    // input order: [wih, whh, bih, bhh] for pep_f, pep_b, hla_f, hla_b
    for (int d = 0; d < 4; ++d) {
        p.wih[d] = (const float*)d_in[2 + 4 * d];
        p.whh[d] = (const float*)d_in[3 + 4 * d];
        p.bih[d] = (const float*)d_in[4 + 4 * d];
        p.bhh[d] = (const float*)d_in[5 + 4 * d];
    }
    const float* w1 = (const float*)d_in[18];
    const float* b1 = (const float*)d_in[19];
    const float* w2 = (const float*)d_in[20];
    const float* b2 = (const float*)d_in[21];

    cudaFuncSetAttribute(lstm_kernel, cudaFuncAttributeMaxDynamicSharedMemorySize,
                         SMEM_BYTES);

    prep_kernel<<<66, NTHR>>>(in_pep, in_hla, p);
    lstm_kernel<<<NBLK, NTHR, SMEM_BYTES>>>(p);
    mlp1_kernel<<<256, NTHR>>>(w1, b1);
    mlp2_kernel<<<1, 1024>>>(w2, b2, (float*)d_out);
}

// round 7
// speedup vs baseline: 1.0382x; 1.0382x over previous
#include <cuda_runtime.h>
#include <cuda_fp16.h>

// ---------------------------------------------------------------------------
// NetMHCpan BiLSTM:  pep BiLSTM (T=15) + HLA BiLSTM (T=372), H=1024,
// then MLP 4096 -> 4096 (relu) -> 1.
//
// Persistent cooperative kernel, 128 CTAs (2 directions x 64), each CTA owns
// 16 hidden units; its 64 gate rows of whh live in SMEM as fp16 (128 KB ->
// occupancy 1 -> all 128 CTAs co-resident). 512 threads/CTA: 16 warps x 4
// gate rows.
//
// Cross-CTA sync: per-(dir,step,cta) WRITE-ONCE flags (distinct addresses ->
// no LTS atomic serialization). Producer: store h -> __threadfence (all
// threads) -> __syncthreads -> tid0 stores its flag. Consumer: 64 threads
// volatile-poll the 64 flags in parallel -> __threadfence -> __syncthreads ->
// __ldcg h.  (Exact fence pattern of the R4 kernel that passed; only the
// same-address atomic + nanosleep gate are replaced.)
// ---------------------------------------------------------------------------

#define H      1024
#define G4     4096
#define LPEP   15
#define LHLA   372
#define GCTA   64     // CTAs per direction
#define NHU    16     // hidden units per CTA
#define NROWS  64     // gate rows per CTA (4 gates * NHU)
#define NTHR   512    // 16 warps
#define NWARP  16
#define NBLK   128    // total persistent CTAs
#define TMAX   400
#define SPIN_LIMIT (1u << 22)   // bounded spin: fail fast instead of deadlock

// SMEM: weights 64*1024 halves (131072 B) + h (4096 B) + gacc (256 B)
#define SMEM_BYTES (NROWS * H * 2 + H * 4 + NROWS * 4)

struct Ptrs {
    const float* wih[4];
    const float* whh[4];
    const float* bih[4];
    const float* bhh[4];
};

// -------------------- device scratch (no allocations allowed) ---------------
__device__ float    g_xg[4 * LHLA * G4];        // input projections (24.4 MB)
__device__ float    g_h[4 * 2 * H];             // per-direction double-buffered h
__device__ unsigned g_flag[4 * TMAX * GCTA];    // write-once per-(d,step,cta) flags
__device__ float    g_h1[G4];                   // MLP hidden activations

// ---------------------------------------------------------------------------
// Prep: blocks 0-63 compute xg[d][t][row] = x_t @ wih.T + bih + bhh;
// block 64 zeroes flags, block 65 zeroes g_h.
// d: 0=pep_f 1=pep_b 2=hla_f 3=hla_b (backward dirs consume reversed input).
// ---------------------------------------------------------------------------
__global__ void prep_kernel(const float* __restrict__ in_pep,
                            const float* __restrict__ in_hla,
                            Ptrs p)
{
    __shared__ float sx[LHLA * 21];    // 31.2 KB
    const int bid = blockIdx.x;
    const int tid = threadIdx.x;

    if (bid >= 64) {
        if (bid == 64) {
            for (int i = tid; i < 4 * TMAX * GCTA; i += 256) g_flag[i] = 0u;
        } else {
            for (int i = tid; i < 4 * 2 * H; i += 256) g_h[i] = 0.0f;
        }
        return;
    }

    const int d  = bid >> 4;          // direction
    const int rb = bid & 15;          // row block (256 rows each)
    const int T  = (d < 2) ? LPEP : LHLA;
    const float* src = (d < 2) ? in_pep : in_hla;
    const bool rev = (d & 1);

    for (int i = tid; i < T * 21; i += 256) {
        int t = i / 21, j = i - t * 21;
        int ts = rev ? (T - 1 - t) : t;
        sx[t * 21 + j] = src[ts * 21 + j];
    }
    __syncthreads();

    const int row = rb * 256 + tid;
    float w[21];
    const float* wp = p.wih[d] + (size_t)row * 21;
#pragma unroll
    for (int j = 0; j < 21; ++j) w[j] = wp[j];
    const float b = p.bih[d][row] + p.bhh[d][row];

    float* out = g_xg + (size_t)d * LHLA * G4 + row;
    for (int t = 0; t < T; ++t) {
        float acc = b;
#pragma unroll
        for (int j = 0; j < 21; ++j) acc = fmaf(w[j], sx[t * 21 + j], acc);
        out[(size_t)t * G4] = acc;
    }
}

// ---------------------------------------------------------------------------
// Persistent BiLSTM kernel (512 threads).
// ---------------------------------------------------------------------------
__global__ void __launch_bounds__(NTHR, 1) lstm_kernel(Ptrs p)
{
    extern __shared__ unsigned char smem[];
    __half2* wt   = (__half2*)smem;                        // [64][512] half2
    float*   h_sm = (float*)(smem + NROWS * H * 2);        // [1024]
    float*   gacc = h_sm + H;                              // [64]

    const int tid  = threadIdx.x;
    const int lane = tid & 31;
    const int warp = tid >> 5;          // 0..15
    const int grp  = blockIdx.x >> 6;   // 0 or 1: direction within phase
    const int gid  = blockIdx.x & 63;   // CTA index within direction group

    for (int phase = 0; phase < 2; ++phase) {
        const int d = phase * 2 + grp;
        const int T = phase ? LHLA : LPEP;
        const float* whh = p.whh[d];

        // ---- load this CTA's 64 gate rows of whh into SMEM as fp16 ----
        for (int r = warp; r < NROWS; r += NWARP) {
            const int u = r & 15, g = r >> 4;
            const float4* src = (const float4*)(whh + ((size_t)(g * H + gid * NHU + u)) * H);
            __half2* dst = wt + r * 512;
            for (int k = lane; k < 256; k += 32) {
                float4 f = src[k];
                dst[2 * k]     = __floats2half2_rn(f.x, f.y);
                dst[2 * k + 1] = __floats2half2_rn(f.z, f.w);
            }
        }
        float c_reg = 0.0f;                                // cell state (tid < 16)
        float* hbuf = g_h + d * 2 * H;
        volatile unsigned* flags = (volatile unsigned*)(g_flag + d * TMAX * GCTA);
        const float* xg_d = g_xg + (size_t)d * LHLA * G4 + gid * NHU;
        __syncthreads();

        for (int t = 0; t < T; ++t) {
            // prefetch xg for this step (independent of h)
            float xg0 = 0.f, xg1 = 0.f, xg2 = 0.f, xg3 = 0.f;
            if (tid < NHU) {
                const float* xp = xg_d + (size_t)t * G4 + tid;
                xg0 = __ldg(xp);
                xg1 = __ldg(xp + H);
                xg2 = __ldg(xp + 2 * H);
                xg3 = __ldg(xp + 3 * H);
            }

            // wait for h(t): 64 threads poll 64 distinct per-CTA flags
            if (t > 0) {
                if (tid < GCTA) {
                    unsigned spins = 0;
                    while (flags[t * GCTA + tid] == 0u && ++spins < SPIN_LIMIT)
                        ;
                    __threadfence();   // acquire (R4-proven pattern)
                }
                __syncthreads();
            }

            // broadcast h(t) into SMEM (L2-coherent loads; L1 may be stale)
            if (tid < 256) {
                const float4* hsrc = (const float4*)(hbuf + (t & 1) * H);
                ((float4*)h_sm)[tid] = __ldcg(hsrc + tid);
            }
            __syncthreads();

            // lane-local h chunk: 4 groups of 8 floats, h[g*256 + lane*8 .. +8]
            float hr[32];
#pragma unroll
            for (int g = 0; g < 4; ++g) {
                ((float4*)hr)[2 * g]     = ((const float4*)h_sm)[g * 64 + lane * 2];
                ((float4*)hr)[2 * g + 1] = ((const float4*)h_sm)[g * 64 + lane * 2 + 1];
            }

            // 4 gate-row dots per warp (rows warp*4 .. warp*4+3)
#pragma unroll
            for (int i = 0; i < 4; ++i) {
                const uint4* wrow = (const uint4*)(wt + (warp * 4 + i) * 512);
                float acc = 0.0f;
#pragma unroll
                for (int g = 0; g < 4; ++g) {
                    // 8 halves: weight cols g*256 + lane*8 .. +7  (uint4 idx g*32+lane)
                    uint4 wq = wrow[g * 32 + lane];
                    float2 f0 = __half22float2(*(const __half2*)&wq.x);
                    float2 f1 = __half22float2(*(const __half2*)&wq.y);
                    float2 f2 = __half22float2(*(const __half2*)&wq.z);
                    float2 f3 = __half22float2(*(const __half2*)&wq.w);
                    acc = fmaf(f0.x, hr[8 * g + 0], acc);
                    acc = fmaf(f0.y, hr[8 * g + 1], acc);
                    acc = fmaf(f1.x, hr[8 * g + 2], acc);
                    acc = fmaf(f1.y, hr[8 * g + 3], acc);
                    acc = fmaf(f2.x, hr[8 * g + 4], acc);
                    acc = fmaf(f2.y, hr[8 * g + 5], acc);
                    acc = fmaf(f3.x, hr[8 * g + 6], acc);
                    acc = fmaf(f3.y, hr[8 * g + 7], acc);
                }
                acc += __shfl_xor_sync(0xffffffffu, acc, 16);
                acc += __shfl_xor_sync(0xffffffffu, acc, 8);
                acc += __shfl_xor_sync(0xffffffffu, acc, 4);
                acc += __shfl_xor_sync(0xffffffffu, acc, 2);
                acc += __shfl_xor_sync(0xffffffffu, acc, 1);
                if (lane == 0) gacc[warp * 4 + i] = acc;   // r = g*16 + u
            }
            __syncthreads();

            // LSTM cell update for this CTA's 16 hidden units
            if (tid < NHU) {
                float zi = gacc[0 * 16 + tid] + xg0;
                float zf = gacc[1 * 16 + tid] + xg1;
                float zg = gacc[2 * 16 + tid] + xg2;
                float zo = gacc[3 * 16 + tid] + xg3;
                float ig = 1.0f / (1.0f + __expf(-zi));
                float fg = 1.0f / (1.0f + __expf(-zf));
                float gg = tanhf(zg);
                float og = 1.0f / (1.0f + __expf(-zo));
                c_reg = fg * c_reg + ig * gg;
                float hn = og * tanhf(c_reg);
                hbuf[((t + 1) & 1) * H + gid * NHU + tid] = hn;
            }
            __threadfence();           // release: h(t+1) visible before flag
            __syncthreads();
            if (tid == 0)
                __stcg((unsigned*)&g_flag[(d * TMAX + t + 1) * GCTA + gid], 1u);
        }
        __syncthreads();               // all reads of wt done before reload
    }
}

// ---------------------------------------------------------------------------
// MLP: h1 = relu(x @ w1.T + b1), y = h1 @ w2.T + b2.
// x = [pep_f, pep_b, hla_f, hla_b]; pep finals in buf 1 (T=15), hla in buf 0.
// ---------------------------------------------------------------------------
__global__ void mlp1_kernel(const float* __restrict__ w1, const float* __restrict__ b1)
{
    __shared__ float sx[G4];
    const int tid = threadIdx.x, lane = tid & 31, warp = tid >> 5;

    for (int k = tid; k < G4; k += 256) {
        int dd = k >> 10;
        int kk = k & 1023;
        int buf = (dd < 2) ? 1 : 0;    // pep T=15 -> buf 1, hla T=372 -> buf 0
        sx[k] = g_h[dd * 2 * H + buf * H + kk];
    }
    __syncthreads();

#pragma unroll
    for (int rep = 0; rep < 2; ++rep) {
        const int j = blockIdx.x * 16 + rep * 8 + warp;
        const float* wrow = w1 + (size_t)j * G4;
        float acc = 0.0f;
#pragma unroll 8
        for (int i = 0; i < 128; ++i)
            acc = fmaf(wrow[i * 32 + lane], sx[i * 32 + lane], acc);
        acc += __shfl_xor_sync(0xffffffffu, acc, 16);
        acc += __shfl_xor_sync(0xffffffffu, acc, 8);
        acc += __shfl_xor_sync(0xffffffffu, acc, 4);
        acc += __shfl_xor_sync(0xffffffffu, acc, 2);
        acc += __shfl_xor_sync(0xffffffffu, acc, 1);
        if (lane == 0) g_h1[j] = fmaxf(acc + b1[j], 0.0f);
    }
}

__global__ void mlp2_kernel(const float* __restrict__ w2, const float* __restrict__ b2,
                            float* __restrict__ out)
{
    __shared__ float red[32];
    const int tid = threadIdx.x, lane = tid & 31, warp = tid >> 5;
    float acc = 0.0f;
    for (int k = tid; k < G4; k += 1024)
        acc = fmaf(g_h1[k], w2[k], acc);
    acc += __shfl_xor_sync(0xffffffffu, acc, 16);
    acc += __shfl_xor_sync(0xffffffffu, acc, 8);
    acc += __shfl_xor_sync(0xffffffffu, acc, 4);
    acc += __shfl_xor_sync(0xffffffffu, acc, 2);
    acc += __shfl_xor_sync(0xffffffffu, acc, 1);
    if (lane == 0) red[warp] = acc;
    __syncthreads();
    if (warp == 0) {
        float v = red[lane];
        v += __shfl_xor_sync(0xffffffffu, v, 16);
        v += __shfl_xor_sync(0xffffffffu, v, 8);
        v += __shfl_xor_sync(0xffffffffu, v, 4);
        v += __shfl_xor_sync(0xffffffffu, v, 2);
        v += __shfl_xor_sync(0xffffffffu, v, 1);
        if (lane == 0) out[0] = v + b2[0];
    }
}

// ---------------------------------------------------------------------------
extern "C" void kernel_launch(void* const* d_in, const int* in_sizes, int n_in,
                              void* d_out, int out_size)
{
    (void)in_sizes; (void)n_in; (void)out_size;

    const float* in_pep = (const float*)d_in[0];
    const float* in_hla = (const float*)d_in[1];

    Ptrs p;
    // input order: [wih, whh, bih, bhh] for pep_f, pep_b, hla_f, hla_b
    for (int d = 0; d < 4; ++d) {
        p.wih[d] = (const float*)d_in[2 + 4 * d];
        p.whh[d] = (const float*)d_in[3 + 4 * d];
        p.bih[d] = (const float*)d_in[4 + 4 * d];
        p.bhh[d] = (const float*)d_in[5 + 4 * d];
    }
    const float* w1 = (const float*)d_in[18];
    const float* b1 = (const float*)d_in[19];
    const float* w2 = (const float*)d_in[20];
    const float* b2 = (const float*)d_in[21];

    cudaFuncSetAttribute(lstm_kernel, cudaFuncAttributeMaxDynamicSharedMemorySize,
                         SMEM_BYTES);

    prep_kernel<<<66, 256>>>(in_pep, in_hla, p);
    lstm_kernel<<<NBLK, NTHR, SMEM_BYTES>>>(p);
    mlp1_kernel<<<256, 256>>>(w1, b1);
    mlp2_kernel<<<1, 1024>>>(w2, b2, (float*)d_out);
}